// round 1
// baseline (speedup 1.0000x reference)
#include <cuda_runtime.h>
#include <cstdint>

#define BB 32
#define NI 1024
#define DIN 1024
#define NOUT 64
#define DOUT 1024

// ---------------- device scratch (no allocations allowed) ----------------
__device__ float g_faT[NI * BB];              // f_a transposed: [i][b]
__device__ float g_xout0[BB * NOUT * DOUT];   // iter-0 output [b][j][h]
__device__ float g_pred[BB * NOUT * DIN];     // pred_x_inp [b][j][d]
__device__ float g_phi1[BB * NI * NOUT];      // phi iter-1 [b][i][j]
__device__ float g_phi1T[NOUT * NI * BB];     // phi iter-1 transposed [j][i][b]

// packed dual-fp32 FMA (Blackwell FFMA2; only reachable via PTX f32x2)
__device__ __forceinline__ float2 ffma2(const float2 a, const float2 b, const float2 c) {
    float2 d;
    asm("fma.rn.f32x2 %0, %1, %2, %3;"
        : "=l"(*reinterpret_cast<unsigned long long*>(&d))
        : "l"(*reinterpret_cast<const unsigned long long*>(&a)),
          "l"(*reinterpret_cast<const unsigned long long*>(&b)),
          "l"(*reinterpret_cast<const unsigned long long*>(&c)));
    return d;
}

// ---------------- K1: f_a = sigmoid(x_inp . W_A + b_A), stored [i][b] ----
__global__ __launch_bounds__(128) void k_fa(const float* __restrict__ x,
                                            const float* __restrict__ WA,
                                            const float* __restrict__ bA) {
    const int row = blockIdx.x;               // b*NI + i
    const int b = row >> 10, i = row & (NI - 1);
    const float4* xr = reinterpret_cast<const float4*>(x) + (size_t)row * (DIN / 4);
    const float4* w4 = reinterpret_cast<const float4*>(WA);
    float s = 0.f;
#pragma unroll
    for (int q = 0; q < 2; q++) {
        int t = threadIdx.x + q * 128;
        float4 xv = xr[t], wv = w4[t];
        s += xv.x * wv.x + xv.y * wv.y + xv.z * wv.z + xv.w * wv.w;
    }
#pragma unroll
    for (int o = 16; o; o >>= 1) s += __shfl_xor_sync(0xffffffffu, s, o);
    __shared__ float red[4];
    if ((threadIdx.x & 31) == 0) red[threadIdx.x >> 5] = s;
    __syncthreads();
    if (threadIdx.x == 0) {
        float tot = red[0] + red[1] + red[2] + red[3] + bA[0];
        g_faT[i * BB + b] = 1.f / (1.f + __expf(-tot));
    }
}

// ---------------- K2: memory einsum x_out[b,j,h] = sum_i A[b,i]*Wm[i,j,h] --
// MODE 0: A[b,i] = f_a[b,i]*(bu[i,j]/64 - bn[i,j]*63/64)  -> g_xout0
// MODE 1: A[b,i] = phi1T[j][i][b]                         -> outp (d_out)
// Block: fixed j (blockIdx.y), 128-wide h strip (blockIdx.x). 128 threads.
// Microtile: 4b x 8h per thread via f32x2 pairs along h.
template <int MODE>
__global__ __launch_bounds__(128) void k_memgemm(const float* __restrict__ Wm,
                                                 const float* __restrict__ bu,
                                                 const float* __restrict__ bn,
                                                 float* __restrict__ outp) {
    const int j = blockIdx.y;
    const int hb = blockIdx.x;
    __shared__ float2 As[32][34];   // [k][b], value duplicated in both halves
    __shared__ float Ws[32][128];   // [k][h]
    const int tid = threadIdx.x;
    const int bgp = tid >> 4;       // 0..7 -> b0 = bgp*4
    const int ht = tid & 15;        // h0 = ht*8
    float2 acc[4][4];
#pragma unroll
    for (int a = 0; a < 4; a++)
#pragma unroll
        for (int h = 0; h < 4; h++) acc[a][h] = make_float2(0.f, 0.f);

    const float* WmB = Wm + (size_t)j * DOUT + (size_t)hb * 128;
    for (int i0 = 0; i0 < NI; i0 += 32) {
#pragma unroll
        for (int q = 0; q < 8; q++) {
            int t = tid + q * 128;
            int r = t >> 5, c4 = t & 31;
            float4 v = *reinterpret_cast<const float4*>(WmB + (size_t)(i0 + r) * (NOUT * DOUT) + c4 * 4);
            *reinterpret_cast<float4*>(&Ws[r][c4 * 4]) = v;
        }
#pragma unroll
        for (int q = 0; q < 8; q++) {
            int t = tid + q * 128;
            int k = t >> 5, bbx = t & 31;
            float v;
            if (MODE == 0) {
                float fa = g_faT[(i0 + k) * BB + bbx];
                int bidx = (i0 + k) * NOUT + j;
                v = fa * (bu[bidx] * (1.0f / 64.0f) - bn[bidx] * (63.0f / 64.0f));
            } else {
                v = g_phi1T[(size_t)j * (NI * BB) + (size_t)(i0 + k) * BB + bbx];
            }
            As[k][bbx] = make_float2(v, v);
        }
        __syncthreads();
#pragma unroll
        for (int k = 0; k < 32; k++) {
            float4 t0 = *reinterpret_cast<const float4*>(&As[k][bgp * 4]);
            float4 t1 = *reinterpret_cast<const float4*>(&As[k][bgp * 4 + 2]);
            float4 w0 = *reinterpret_cast<const float4*>(&Ws[k][ht * 8]);
            float4 w1 = *reinterpret_cast<const float4*>(&Ws[k][ht * 8 + 4]);
            float2 av[4] = {make_float2(t0.x, t0.y), make_float2(t0.z, t0.w),
                            make_float2(t1.x, t1.y), make_float2(t1.z, t1.w)};
            float2 wp[4] = {make_float2(w0.x, w0.y), make_float2(w0.z, w0.w),
                            make_float2(w1.x, w1.y), make_float2(w1.z, w1.w)};
#pragma unroll
            for (int a = 0; a < 4; a++)
#pragma unroll
                for (int h = 0; h < 4; h++) acc[a][h] = ffma2(av[a], wp[h], acc[a][h]);
        }
        __syncthreads();
    }
    float* dst = (MODE == 0) ? g_xout0 : outp;
#pragma unroll
    for (int a = 0; a < 4; a++) {
        int b = bgp * 4 + a;
        float* o = dst + ((size_t)(b * NOUT + j)) * DOUT + hb * 128 + ht * 8;
        *reinterpret_cast<float4*>(o) =
            make_float4(acc[a][0].x, acc[a][0].y, acc[a][1].x, acc[a][1].y);
        *reinterpret_cast<float4*>(o + 4) =
            make_float4(acc[a][2].x, acc[a][2].y, acc[a][3].x, acc[a][3].y);
    }
}

// ---------------- K3: pred[b,j,d] = sum_h xout0[b,j,h]*WG[h,d] + bG[d] -----
__global__ __launch_bounds__(128) void k_pred(const float* __restrict__ WG,
                                              const float* __restrict__ bG) {
    const int db = blockIdx.x;  // 0..7  (128 d each)
    const int jt = blockIdx.y;  // 0..1  (32 j each)
    const int b = blockIdx.z;   // 0..31
    __shared__ float2 As[32][34];  // [k(h)][j] duplicated
    __shared__ float Ws[32][128];  // [k(h)][d]
    const int tid = threadIdx.x;
    const int rg = tid >> 4, ht = tid & 15;
    float2 acc[4][4];
#pragma unroll
    for (int a = 0; a < 4; a++)
#pragma unroll
        for (int h = 0; h < 4; h++) acc[a][h] = make_float2(0.f, 0.f);

    const float* Arow = g_xout0 + ((size_t)(b * NOUT + jt * 32)) * DOUT;
    const float* WGB = WG + (size_t)db * 128;
    for (int h0 = 0; h0 < DOUT; h0 += 32) {
#pragma unroll
        for (int q = 0; q < 8; q++) {
            int t = tid + q * 128;
            int r = t >> 5, c4 = t & 31;
            float4 v = *reinterpret_cast<const float4*>(WGB + (size_t)(h0 + r) * DIN + c4 * 4);
            *reinterpret_cast<float4*>(&Ws[r][c4 * 4]) = v;
        }
#pragma unroll
        for (int q = 0; q < 2; q++) {
            int f4 = tid + q * 128;  // 0..255
            int jj = f4 >> 3, h4 = f4 & 7;
            float4 v = *reinterpret_cast<const float4*>(Arow + (size_t)jj * DOUT + h0 + h4 * 4);
            As[h4 * 4 + 0][jj] = make_float2(v.x, v.x);
            As[h4 * 4 + 1][jj] = make_float2(v.y, v.y);
            As[h4 * 4 + 2][jj] = make_float2(v.z, v.z);
            As[h4 * 4 + 3][jj] = make_float2(v.w, v.w);
        }
        __syncthreads();
#pragma unroll
        for (int k = 0; k < 32; k++) {
            float4 t0 = *reinterpret_cast<const float4*>(&As[k][rg * 4]);
            float4 t1 = *reinterpret_cast<const float4*>(&As[k][rg * 4 + 2]);
            float4 w0 = *reinterpret_cast<const float4*>(&Ws[k][ht * 8]);
            float4 w1 = *reinterpret_cast<const float4*>(&Ws[k][ht * 8 + 4]);
            float2 av[4] = {make_float2(t0.x, t0.y), make_float2(t0.z, t0.w),
                            make_float2(t1.x, t1.y), make_float2(t1.z, t1.w)};
            float2 wp[4] = {make_float2(w0.x, w0.y), make_float2(w0.z, w0.w),
                            make_float2(w1.x, w1.y), make_float2(w1.z, w1.w)};
#pragma unroll
            for (int a = 0; a < 4; a++)
#pragma unroll
                for (int h = 0; h < 4; h++) acc[a][h] = ffma2(av[a], wp[h], acc[a][h]);
        }
        __syncthreads();
    }
    const int d0 = db * 128 + ht * 8;
    float4 bg0 = *reinterpret_cast<const float4*>(bG + d0);
    float4 bg1 = *reinterpret_cast<const float4*>(bG + d0 + 4);
#pragma unroll
    for (int a = 0; a < 4; a++) {
        int jj = jt * 32 + rg * 4 + a;
        float* o = g_pred + ((size_t)(b * NOUT + jj)) * DIN + d0;
        *reinterpret_cast<float4*>(o) =
            make_float4(acc[a][0].x + bg0.x, acc[a][0].y + bg0.y,
                        acc[a][1].x + bg0.z, acc[a][1].y + bg0.w);
        *reinterpret_cast<float4*>(o + 4) =
            make_float4(acc[a][2].x + bg1.x, acc[a][2].y + bg1.y,
                        acc[a][3].x + bg1.z, acc[a][3].y + bg1.w);
    }
}

// ---------------- K4: S = (x_inp . pred^T)/32, softmax over j, phi1 -------
// Block: fixed b, 64-row i-tile, all 64 j. 256 threads, micro 4i x 4j.
__global__ __launch_bounds__(256) void k_sim(const float* __restrict__ x,
                                             const float* __restrict__ bu,
                                             const float* __restrict__ bn) {
    const int it = blockIdx.x;  // 0..15
    const int b = blockIdx.y;   // 0..31
    __shared__ float2 As[32][68];  // [d][i] duplicated
    __shared__ float Bs[32][68];   // [d][j]
    __shared__ float Ss[64][64];
    const int tid = threadIdx.x;
    const int ig = tid >> 4, jt = tid & 15;
    float2 acc[4][2];
#pragma unroll
    for (int a = 0; a < 4; a++) { acc[a][0] = make_float2(0.f, 0.f); acc[a][1] = make_float2(0.f, 0.f); }

    const float* Ar = x + ((size_t)b * NI + (size_t)it * 64) * DIN;
    const float* Br = g_pred + (size_t)b * NOUT * DIN;
    for (int d0 = 0; d0 < DIN; d0 += 32) {
#pragma unroll
        for (int q = 0; q < 2; q++) {
            int f4 = tid + q * 256;  // 0..511 -> 64 i x 8 f4
            int ii = f4 >> 3, d4 = f4 & 7;
            float4 v = *reinterpret_cast<const float4*>(Ar + (size_t)ii * DIN + d0 + d4 * 4);
            As[d4 * 4 + 0][ii] = make_float2(v.x, v.x);
            As[d4 * 4 + 1][ii] = make_float2(v.y, v.y);
            As[d4 * 4 + 2][ii] = make_float2(v.z, v.z);
            As[d4 * 4 + 3][ii] = make_float2(v.w, v.w);
        }
#pragma unroll
        for (int q = 0; q < 2; q++) {
            int f4 = tid + q * 256;  // 64 j x 8 f4
            int jj = f4 >> 3, d4 = f4 & 7;
            float4 v = *reinterpret_cast<const float4*>(Br + (size_t)jj * DIN + d0 + d4 * 4);
            Bs[d4 * 4 + 0][jj] = v.x;
            Bs[d4 * 4 + 1][jj] = v.y;
            Bs[d4 * 4 + 2][jj] = v.z;
            Bs[d4 * 4 + 3][jj] = v.w;
        }
        __syncthreads();
#pragma unroll
        for (int k = 0; k < 32; k++) {
            float4 t0 = *reinterpret_cast<const float4*>(&As[k][ig * 4]);
            float4 t1 = *reinterpret_cast<const float4*>(&As[k][ig * 4 + 2]);
            float4 wv = *reinterpret_cast<const float4*>(&Bs[k][jt * 4]);
            float2 av[4] = {make_float2(t0.x, t0.y), make_float2(t0.z, t0.w),
                            make_float2(t1.x, t1.y), make_float2(t1.z, t1.w)};
            float2 wp0 = make_float2(wv.x, wv.y), wp1 = make_float2(wv.z, wv.w);
#pragma unroll
            for (int a = 0; a < 4; a++) {
                acc[a][0] = ffma2(av[a], wp0, acc[a][0]);
                acc[a][1] = ffma2(av[a], wp1, acc[a][1]);
            }
        }
        __syncthreads();
    }
    const float scale = 0.03125f;  // 1024^-0.5
#pragma unroll
    for (int a = 0; a < 4; a++) {
        *reinterpret_cast<float4*>(&Ss[ig * 4 + a][jt * 4]) =
            make_float4(acc[a][0].x * scale, acc[a][0].y * scale,
                        acc[a][1].x * scale, acc[a][1].y * scale);
    }
    __syncthreads();
    // softmax over 64 j + phi1, one warp per row, 8 rows per warp
    const int warp = tid >> 5, lane = tid & 31;
    for (int rr = 0; rr < 8; rr++) {
        int r = warp * 8 + rr;
        int i_glob = it * 64 + r;
        float v0 = Ss[r][lane], v1 = Ss[r][lane + 32];
        float m = fmaxf(v0, v1);
#pragma unroll
        for (int o = 16; o; o >>= 1) m = fmaxf(m, __shfl_xor_sync(0xffffffffu, m, o));
        float e0 = __expf(v0 - m), e1 = __expf(v1 - m);
        float s = e0 + e1;
#pragma unroll
        for (int o = 16; o; o >>= 1) s += __shfl_xor_sync(0xffffffffu, s, o);
        float inv = 1.f / s;
        float fa = g_faT[i_glob * BB + b];
        int bi0 = i_glob * NOUT + lane;
        float bu0 = bu[bi0], bu1 = bu[bi0 + 32];
        float bn0 = bn[bi0], bn1 = bn[bi0 + 32];
        float R0 = e0 * inv, R1 = e1 * inv;
        size_t base = ((size_t)b * NI + i_glob) * NOUT;
        g_phi1[base + lane] = fa * ((bu0 + bn0) * R0 - bn0);
        g_phi1[base + lane + 32] = fa * ((bu1 + bn1) * R1 - bn1);
    }
}

// ---------------- K5: transpose phi1 [b][i][j] -> [j][i][b] ---------------
__global__ __launch_bounds__(256) void k_tr() {
    const int i = blockIdx.x;  // 0..1023
    __shared__ float t[32][65];
    const int tid = threadIdx.x;
#pragma unroll
    for (int q = 0; q < 8; q++) {
        int idx = tid + q * 256;
        int bb = idx >> 6, j = idx & 63;
        t[bb][j] = g_phi1[((size_t)bb * NI + i) * NOUT + j];
    }
    __syncthreads();
#pragma unroll
    for (int q = 0; q < 8; q++) {
        int idx = tid + q * 256;
        int j = idx >> 5, bb = idx & 31;
        g_phi1T[((size_t)j * NI + i) * BB + bb] = t[bb][j];
    }
}

// ---------------- launch ---------------------------------------------------
extern "C" void kernel_launch(void* const* d_in, const int* in_sizes, int n_in,
                              void* d_out, int out_size) {
    const float* x  = (const float*)d_in[0];
    const float* WA = (const float*)d_in[1];
    const float* bA = (const float*)d_in[2];
    const float* Wm = (const float*)d_in[3];
    const float* WG = (const float*)d_in[4];
    const float* bG = (const float*)d_in[5];
    const float* bu = (const float*)d_in[6];
    const float* bn = (const float*)d_in[7];
    float* out = (float*)d_out;

    k_fa<<<BB * NI, 128>>>(x, WA, bA);
    k_memgemm<0><<<dim3(8, 64), 128>>>(Wm, bu, bn, nullptr);
    k_pred<<<dim3(8, 2, 32), 128>>>(WG, bG);
    k_sim<<<dim3(16, 32), 256>>>(x, bu, bn);
    k_tr<<<NI, 256>>>();
    k_memgemm<1><<<dim3(8, 64), 128>>>(Wm, bu, bn, out);
}

// round 3
// speedup vs baseline: 1.1227x; 1.1227x over previous
#include <cuda_runtime.h>
#include <cstdint>

#define BB 32
#define NI 1024
#define DIN 1024
#define NOUT 64
#define DOUT 1024
#define KT 16

// ---------------- device scratch ----------------
__device__ float g_faT[NI * BB];              // f_a transposed [i][b]
__device__ float g_xout0[BB * NOUT * DOUT];   // iter-0 output [b][j][h] (2048x1024)
__device__ float g_pred[BB * NOUT * DIN];     // pred [b][j][d]       (2048x1024)
__device__ float g_phi1[BB * NI * NOUT];      // phi iter-1 [b][i][j]
__device__ float g_phiT[NOUT * NI * BB];      // phi transposed [j][i][b] (both iters)

// packed dual-fp32 FMA (FFMA2, PTX-only)
__device__ __forceinline__ float2 ffma2(const float2 a, const float2 b, const float2 c) {
    float2 d;
    asm("fma.rn.f32x2 %0, %1, %2, %3;"
        : "=l"(*reinterpret_cast<unsigned long long*>(&d))
        : "l"(*reinterpret_cast<const unsigned long long*>(&a)),
          "l"(*reinterpret_cast<const unsigned long long*>(&b)),
          "l"(*reinterpret_cast<const unsigned long long*>(&c)));
    return d;
}

// ---------------- K1: f_a = sigmoid(x . W_A + b_A) -> g_faT[i][b] ---------
__global__ __launch_bounds__(256) void k_fa(const float* __restrict__ x,
                                            const float* __restrict__ WA,
                                            const float* __restrict__ bA) {
    const int row = blockIdx.x * 8 + (threadIdx.x >> 5);   // b*NI + i
    const int lane = threadIdx.x & 31;
    const float4* xr = reinterpret_cast<const float4*>(x) + (size_t)row * (DIN / 4);
    const float4* w4 = reinterpret_cast<const float4*>(WA);
    float s = 0.f;
#pragma unroll
    for (int q = 0; q < 8; q++) {
        float4 xv = xr[lane + q * 32], wv = w4[lane + q * 32];
        s += xv.x * wv.x + xv.y * wv.y + xv.z * wv.z + xv.w * wv.w;
    }
#pragma unroll
    for (int o = 16; o; o >>= 1) s += __shfl_xor_sync(0xffffffffu, s, o);
    if (lane == 0) {
        const int b = row >> 10, i = row & (NI - 1);
        float tot = s + bA[0];
        g_faT[i * BB + b] = 1.f / (1.f + __expf(-tot));
    }
}

// ---------------- K2: phi0 transposed [j][i][b] ---------------------------
__global__ __launch_bounds__(256) void k_phi0(const float* __restrict__ bu,
                                              const float* __restrict__ bn) {
    const int p = blockIdx.x * 256 + threadIdx.x;   // (j,i)
    const int j = p >> 10, i = p & (NI - 1);
    const float cu = bu[i * NOUT + j] * (1.0f / 64.0f) - bn[i * NOUT + j] * (63.0f / 64.0f);
    const float4* fa = reinterpret_cast<const float4*>(&g_faT[i * BB]);
    float4* dst = reinterpret_cast<float4*>(&g_phiT[((size_t)j * NI + i) * BB]);
#pragma unroll
    for (int q = 0; q < 8; q++) {
        float4 v = fa[q];
        dst[q] = make_float4(v.x * cu, v.y * cu, v.z * cu, v.w * cu);
    }
}

// ---------------- K3: memory einsum out[b,j,h] = sum_i phiT[j,i,b]*Wm[i,j,h]
// Block: (hb 0..7, j 0..63). 128 threads. Tile: 32b x 128h, K-tile 16 (i).
// Thread micro: 4b x 8h, acc as f32x2 along h.
template <int MODE>
__global__ __launch_bounds__(128) void k_mem(const float* __restrict__ Wm,
                                             float* __restrict__ outp) {
    const int j = blockIdx.y, hb = blockIdx.x;
    __shared__ float2 Ad[2][KT][BB];     // dup pairs [k][b]   8KB
    __shared__ float  Bs[2][KT][128];    // [k][h]            16KB
    const int tid = threadIdx.x, lane = tid & 31, w = tid >> 5;
    const int mt = lane >> 3, nl = lane & 7;
    const int m0 = (w & 1) * 16 + mt * 4;
    const int n0 = (w >> 1) * 64 + nl * 8;
    // fill mapping
    const int fbr = tid >> 3, fbc = tid & 7;        // B: row 0..15, col4 base (4x q-stride 8)
    const int far_ = tid >> 3, fac = (tid & 7) * 4; // A: row 0..15, 4 b's
    const float* WmB = Wm + (size_t)j * DOUT + (size_t)hb * 128;
    const float* Ab = g_phiT + (size_t)j * (NI * BB);

    float2 acc[4][4];
#pragma unroll
    for (int a = 0; a < 4; a++)
#pragma unroll
        for (int h = 0; h < 4; h++) acc[a][h] = make_float2(0.f, 0.f);

    float4 bR[4]; float4 aR;
    // prologue: load+store tile 0
#pragma unroll
    for (int q = 0; q < 4; q++)
        bR[q] = *reinterpret_cast<const float4*>(WmB + (size_t)fbr * (NOUT * DOUT) + (size_t)(fbc + q * 8) * 4);
    aR = *reinterpret_cast<const float4*>(Ab + (size_t)far_ * BB + fac);
#pragma unroll
    for (int q = 0; q < 4; q++)
        *reinterpret_cast<float4*>(&Bs[0][fbr][(fbc + q * 8) * 4]) = bR[q];
    Ad[0][far_][fac + 0] = make_float2(aR.x, aR.x);
    Ad[0][far_][fac + 1] = make_float2(aR.y, aR.y);
    Ad[0][far_][fac + 2] = make_float2(aR.z, aR.z);
    Ad[0][far_][fac + 3] = make_float2(aR.w, aR.w);
    __syncthreads();

    const int NT = NI / KT;  // 64
    for (int t = 0; t < NT; t++) {
        const int cur = t & 1;
        const bool more = (t + 1 < NT);
        if (more) {
            const int i0 = (t + 1) * KT;
#pragma unroll
            for (int q = 0; q < 4; q++)
                bR[q] = *reinterpret_cast<const float4*>(WmB + (size_t)(i0 + fbr) * (NOUT * DOUT) + (size_t)(fbc + q * 8) * 4);
            aR = *reinterpret_cast<const float4*>(Ab + (size_t)(i0 + far_) * BB + fac);
        }
        const float2* Adc = &Ad[cur][0][0];
        const float* Bsc = &Bs[cur][0][0];
#pragma unroll
        for (int k = 0; k < KT; k++) {
            float4 a01 = *reinterpret_cast<const float4*>(Adc + k * BB + m0);
            float4 a23 = *reinterpret_cast<const float4*>(Adc + k * BB + m0 + 2);
            float4 b0 = *reinterpret_cast<const float4*>(Bsc + k * 128 + n0);
            float4 b1 = *reinterpret_cast<const float4*>(Bsc + k * 128 + n0 + 4);
            float2 ap[4] = {make_float2(a01.x, a01.y), make_float2(a01.z, a01.w),
                            make_float2(a23.x, a23.y), make_float2(a23.z, a23.w)};
            float2 bp[4] = {make_float2(b0.x, b0.y), make_float2(b0.z, b0.w),
                            make_float2(b1.x, b1.y), make_float2(b1.z, b1.w)};
#pragma unroll
            for (int a = 0; a < 4; a++)
#pragma unroll
                for (int h = 0; h < 4; h++) acc[a][h] = ffma2(ap[a], bp[h], acc[a][h]);
        }
        if (more) {
            const int nxt = 1 - cur;
#pragma unroll
            for (int q = 0; q < 4; q++)
                *reinterpret_cast<float4*>(&Bs[nxt][fbr][(fbc + q * 8) * 4]) = bR[q];
            Ad[nxt][far_][fac + 0] = make_float2(aR.x, aR.x);
            Ad[nxt][far_][fac + 1] = make_float2(aR.y, aR.y);
            Ad[nxt][far_][fac + 2] = make_float2(aR.z, aR.z);
            Ad[nxt][far_][fac + 3] = make_float2(aR.w, aR.w);
        }
        __syncthreads();
    }
    float* dst = (MODE == 0) ? g_xout0 : outp;
#pragma unroll
    for (int a = 0; a < 4; a++) {
        const int b = m0 + a;
        float* o = dst + ((size_t)(b * NOUT + j)) * DOUT + hb * 128 + n0;
        *reinterpret_cast<float4*>(o) =
            make_float4(acc[a][0].x, acc[a][0].y, acc[a][1].x, acc[a][1].y);
        *reinterpret_cast<float4*>(o + 4) =
            make_float4(acc[a][2].x, acc[a][2].y, acc[a][3].x, acc[a][3].y);
    }
}

// ---------------- K4: pred = xout0 @ WG + bG  (2048x1024x1024 GEMM) -------
// Block: (nb 0..7, mb 0..31). 256 threads. Tile 64m x 128n, K-tile 16 (h).
__global__ __launch_bounds__(256) void k_pred(const float* __restrict__ WG,
                                              const float* __restrict__ bG) {
    const int nb = blockIdx.x, mb = blockIdx.y;
    const int mBase = mb * 64, nBase = nb * 128;
    __shared__ float2 Ad[2][KT][64];     // 16KB
    __shared__ float  Bs[2][KT][128];    // 16KB
    const int tid = threadIdx.x, lane = tid & 31, w = tid >> 5;
    const int mt = lane >> 3, nl = lane & 7;
    const int m0 = (w & 3) * 16 + mt * 4;
    const int n0 = (w >> 2) * 64 + nl * 8;
    const int fam = tid & 63, fak = (tid >> 6) * 4;   // A: m, 4 k's
    const int fbr = tid >> 4, fbc = tid & 15;         // B: row, col4 base

    float2 acc[4][4];
#pragma unroll
    for (int a = 0; a < 4; a++)
#pragma unroll
        for (int h = 0; h < 4; h++) acc[a][h] = make_float2(0.f, 0.f);

    float4 aR; float4 bR[2];
    aR = *reinterpret_cast<const float4*>(g_xout0 + (size_t)(mBase + fam) * DOUT + fak);
#pragma unroll
    for (int q = 0; q < 2; q++)
        bR[q] = *reinterpret_cast<const float4*>(WG + (size_t)fbr * DIN + nBase + (fbc + q * 16) * 4);
    Ad[0][fak + 0][fam] = make_float2(aR.x, aR.x);
    Ad[0][fak + 1][fam] = make_float2(aR.y, aR.y);
    Ad[0][fak + 2][fam] = make_float2(aR.z, aR.z);
    Ad[0][fak + 3][fam] = make_float2(aR.w, aR.w);
#pragma unroll
    for (int q = 0; q < 2; q++)
        *reinterpret_cast<float4*>(&Bs[0][fbr][(fbc + q * 16) * 4]) = bR[q];
    __syncthreads();

    const int NT = DOUT / KT;
    for (int t = 0; t < NT; t++) {
        const int cur = t & 1;
        const bool more = (t + 1 < NT);
        if (more) {
            const int h0 = (t + 1) * KT;
            aR = *reinterpret_cast<const float4*>(g_xout0 + (size_t)(mBase + fam) * DOUT + h0 + fak);
#pragma unroll
            for (int q = 0; q < 2; q++)
                bR[q] = *reinterpret_cast<const float4*>(WG + (size_t)(h0 + fbr) * DIN + nBase + (fbc + q * 16) * 4);
        }
        const float2* Adc = &Ad[cur][0][0];
        const float* Bsc = &Bs[cur][0][0];
#pragma unroll
        for (int k = 0; k < KT; k++) {
            float4 a01 = *reinterpret_cast<const float4*>(Adc + k * 64 + m0);
            float4 a23 = *reinterpret_cast<const float4*>(Adc + k * 64 + m0 + 2);
            float4 b0 = *reinterpret_cast<const float4*>(Bsc + k * 128 + n0);
            float4 b1 = *reinterpret_cast<const float4*>(Bsc + k * 128 + n0 + 4);
            float2 ap[4] = {make_float2(a01.x, a01.y), make_float2(a01.z, a01.w),
                            make_float2(a23.x, a23.y), make_float2(a23.z, a23.w)};
            float2 bp[4] = {make_float2(b0.x, b0.y), make_float2(b0.z, b0.w),
                            make_float2(b1.x, b1.y), make_float2(b1.z, b1.w)};
#pragma unroll
            for (int a = 0; a < 4; a++)
#pragma unroll
                for (int h = 0; h < 4; h++) acc[a][h] = ffma2(ap[a], bp[h], acc[a][h]);
        }
        if (more) {
            const int nxt = 1 - cur;
            Ad[nxt][fak + 0][fam] = make_float2(aR.x, aR.x);
            Ad[nxt][fak + 1][fam] = make_float2(aR.y, aR.y);
            Ad[nxt][fak + 2][fam] = make_float2(aR.z, aR.z);
            Ad[nxt][fak + 3][fam] = make_float2(aR.w, aR.w);
#pragma unroll
            for (int q = 0; q < 2; q++)
                *reinterpret_cast<float4*>(&Bs[nxt][fbr][(fbc + q * 16) * 4]) = bR[q];
        }
        __syncthreads();
    }
    const float4 bg0 = *reinterpret_cast<const float4*>(bG + nBase + n0);
    const float4 bg1 = *reinterpret_cast<const float4*>(bG + nBase + n0 + 4);
#pragma unroll
    for (int a = 0; a < 4; a++) {
        float* o = g_pred + (size_t)(mBase + m0 + a) * DIN + nBase + n0;
        *reinterpret_cast<float4*>(o) =
            make_float4(acc[a][0].x + bg0.x, acc[a][0].y + bg0.y,
                        acc[a][1].x + bg0.z, acc[a][1].y + bg0.w);
        *reinterpret_cast<float4*>(o + 4) =
            make_float4(acc[a][2].x + bg1.x, acc[a][2].y + bg1.y,
                        acc[a][3].x + bg1.z, acc[a][3].y + bg1.w);
    }
}

// ---------------- K5: S=(x.pred^T)/32 -> softmax -> phi1[b][i][j] ---------
// Block: (it 0..7 [128 i], b 0..31). 256 threads. Tile 128i x 64j, K-tile 16.
__global__ __launch_bounds__(256) void k_sim(const float* __restrict__ x,
                                             const float* __restrict__ bu,
                                             const float* __restrict__ bn) {
    const int i0 = blockIdx.x * 128;
    const int b = blockIdx.y;
    __shared__ float2 Ad[2][KT][128];    // 32KB
    __shared__ float  Bs[2][KT][NOUT];   //  8KB
    const int tid = threadIdx.x, lane = tid & 31, w = tid >> 5;
    const int mt = lane >> 3, nl = lane & 7;
    const int m0 = w * 16 + mt * 4;
    const int n0 = nl * 8;
    const int fai = tid & 127, fak = (tid >> 7) * 8;   // A: i, 8 k's (2 f4)
    const int fbj = tid & 63, fbk = (tid >> 6) * 4;    // B: j, 4 k's

    const float* Arow = x + ((size_t)b * NI + i0 + fai) * DIN;
    const float* Brow = g_pred + ((size_t)b * NOUT + fbj) * DIN;

    float2 acc[4][4];
#pragma unroll
    for (int a = 0; a < 4; a++)
#pragma unroll
        for (int h = 0; h < 4; h++) acc[a][h] = make_float2(0.f, 0.f);

    float4 aR[2]; float4 bR;
#pragma unroll
    for (int q = 0; q < 2; q++)
        aR[q] = *reinterpret_cast<const float4*>(Arow + fak + q * 4);
    bR = *reinterpret_cast<const float4*>(Brow + fbk);
#pragma unroll
    for (int q = 0; q < 2; q++) {
        Ad[0][fak + q * 4 + 0][fai] = make_float2(aR[q].x, aR[q].x);
        Ad[0][fak + q * 4 + 1][fai] = make_float2(aR[q].y, aR[q].y);
        Ad[0][fak + q * 4 + 2][fai] = make_float2(aR[q].z, aR[q].z);
        Ad[0][fak + q * 4 + 3][fai] = make_float2(aR[q].w, aR[q].w);
    }
    Bs[0][fbk + 0][fbj] = bR.x;
    Bs[0][fbk + 1][fbj] = bR.y;
    Bs[0][fbk + 2][fbj] = bR.z;
    Bs[0][fbk + 3][fbj] = bR.w;
    __syncthreads();

    const int NT = DIN / KT;
    for (int t = 0; t < NT; t++) {
        const int cur = t & 1;
        const bool more = (t + 1 < NT);
        if (more) {
            const int d0 = (t + 1) * KT;
#pragma unroll
            for (int q = 0; q < 2; q++)
                aR[q] = *reinterpret_cast<const float4*>(Arow + d0 + fak + q * 4);
            bR = *reinterpret_cast<const float4*>(Brow + d0 + fbk);
        }
        const float2* Adc = &Ad[cur][0][0];
        const float* Bsc = &Bs[cur][0][0];
#pragma unroll
        for (int k = 0; k < KT; k++) {
            float4 a01 = *reinterpret_cast<const float4*>(Adc + k * 128 + m0);
            float4 a23 = *reinterpret_cast<const float4*>(Adc + k * 128 + m0 + 2);
            float4 b0 = *reinterpret_cast<const float4*>(Bsc + k * NOUT + n0);
            float4 b1 = *reinterpret_cast<const float4*>(Bsc + k * NOUT + n0 + 4);
            float2 ap[4] = {make_float2(a01.x, a01.y), make_float2(a01.z, a01.w),
                            make_float2(a23.x, a23.y), make_float2(a23.z, a23.w)};
            float2 bp[4] = {make_float2(b0.x, b0.y), make_float2(b0.z, b0.w),
                            make_float2(b1.x, b1.y), make_float2(b1.z, b1.w)};
#pragma unroll
            for (int a = 0; a < 4; a++)
#pragma unroll
                for (int h = 0; h < 4; h++) acc[a][h] = ffma2(ap[a], bp[h], acc[a][h]);
        }
        if (more) {
            const int nxt = 1 - cur;
#pragma unroll
            for (int q = 0; q < 2; q++) {
                Ad[nxt][fak + q * 4 + 0][fai] = make_float2(aR[q].x, aR[q].x);
                Ad[nxt][fak + q * 4 + 1][fai] = make_float2(aR[q].y, aR[q].y);
                Ad[nxt][fak + q * 4 + 2][fai] = make_float2(aR[q].z, aR[q].z);
                Ad[nxt][fak + q * 4 + 3][fai] = make_float2(aR[q].w, aR[q].w);
            }
            Bs[nxt][fbk + 0][fbj] = bR.x;
            Bs[nxt][fbk + 1][fbj] = bR.y;
            Bs[nxt][fbk + 2][fbj] = bR.z;
            Bs[nxt][fbk + 3][fbj] = bR.w;
        }
        __syncthreads();
    }

    // softmax over 64 j within lane-octets (lanes share (w,mt); nl spans 8)
    const float scale = 0.03125f;  // 1024^-0.5
#pragma unroll
    for (int a = 0; a < 4; a++) {
        const int ig = i0 + m0 + a;
        float v[8] = {acc[a][0].x * scale, acc[a][0].y * scale,
                      acc[a][1].x * scale, acc[a][1].y * scale,
                      acc[a][2].x * scale, acc[a][2].y * scale,
                      acc[a][3].x * scale, acc[a][3].y * scale};
        float mx = v[0];
#pragma unroll
        for (int q = 1; q < 8; q++) mx = fmaxf(mx, v[q]);
        mx = fmaxf(mx, __shfl_xor_sync(0xffffffffu, mx, 1));
        mx = fmaxf(mx, __shfl_xor_sync(0xffffffffu, mx, 2));
        mx = fmaxf(mx, __shfl_xor_sync(0xffffffffu, mx, 4));
        float e[8], s = 0.f;
#pragma unroll
        for (int q = 0; q < 8; q++) { e[q] = __expf(v[q] - mx); s += e[q]; }
        s += __shfl_xor_sync(0xffffffffu, s, 1);
        s += __shfl_xor_sync(0xffffffffu, s, 2);
        s += __shfl_xor_sync(0xffffffffu, s, 4);
        const float inv = 1.f / s;
        const float fa = g_faT[ig * BB + b];
        const float4 bu0 = *reinterpret_cast<const float4*>(bu + (size_t)ig * NOUT + n0);
        const float4 bu1 = *reinterpret_cast<const float4*>(bu + (size_t)ig * NOUT + n0 + 4);
        const float4 bn0 = *reinterpret_cast<const float4*>(bn + (size_t)ig * NOUT + n0);
        const float4 bn1 = *reinterpret_cast<const float4*>(bn + (size_t)ig * NOUT + n0 + 4);
        float* o = g_phi1 + ((size_t)b * NI + ig) * NOUT + n0;
        *reinterpret_cast<float4*>(o) = make_float4(
            fa * ((bu0.x + bn0.x) * e[0] * inv - bn0.x),
            fa * ((bu0.y + bn0.y) * e[1] * inv - bn0.y),
            fa * ((bu0.z + bn0.z) * e[2] * inv - bn0.z),
            fa * ((bu0.w + bn0.w) * e[3] * inv - bn0.w));
        *reinterpret_cast<float4*>(o + 4) = make_float4(
            fa * ((bu1.x + bn1.x) * e[4] * inv - bn1.x),
            fa * ((bu1.y + bn1.y) * e[5] * inv - bn1.y),
            fa * ((bu1.z + bn1.z) * e[6] * inv - bn1.z),
            fa * ((bu1.w + bn1.w) * e[7] * inv - bn1.w));
    }
}

// ---------------- K6: transpose phi1 [b][i][j] -> phiT [j][i][b] ----------
__global__ __launch_bounds__(256) void k_tr() {
    const int i = blockIdx.x;
    __shared__ float t[32][65];
    const int tid = threadIdx.x;
#pragma unroll
    for (int q = 0; q < 8; q++) {
        int idx = tid + q * 256;
        int bb = idx >> 6, j = idx & 63;
        t[bb][j] = g_phi1[((size_t)bb * NI + i) * NOUT + j];
    }
    __syncthreads();
#pragma unroll
    for (int q = 0; q < 8; q++) {
        int idx = tid + q * 256;
        int j = idx >> 5, bb = idx & 31;
        g_phiT[((size_t)j * NI + i) * BB + bb] = t[bb][j];
    }
}

// ---------------- launch ---------------------------------------------------
extern "C" void kernel_launch(void* const* d_in, const int* in_sizes, int n_in,
                              void* d_out, int out_size) {
    const float* x  = (const float*)d_in[0];
    const float* WA = (const float*)d_in[1];
    const float* bA = (const float*)d_in[2];
    const float* Wm = (const float*)d_in[3];
    const float* WG = (const float*)d_in[4];
    const float* bG = (const float*)d_in[5];
    const float* bu = (const float*)d_in[6];
    const float* bn = (const float*)d_in[7];
    float* out = (float*)d_out;

    k_fa<<<4096, 256>>>(x, WA, bA);
    k_phi0<<<256, 256>>>(bu, bn);
    k_mem<0><<<dim3(8, 64), 128>>>(Wm, nullptr);
    k_pred<<<dim3(8, 32), 256>>>(WG, bG);
    k_sim<<<dim3(8, 32), 256>>>(x, bu, bn);
    k_tr<<<NI, 256>>>();
    k_mem<1><<<dim3(8, 64), 128>>>(Wm, out);
}

// round 4
// speedup vs baseline: 1.9926x; 1.7748x over previous
#include <cuda_runtime.h>
#include <cstdint>

#define BB 32
#define NI 1024
#define DIN 1024
#define NOUT 64
#define DOUT 1024
#define KT 16

// ---------------- device scratch ----------------
__device__ float g_faT[NI * BB];              // f_a transposed [i][b]
__device__ float g_xout0[BB * NOUT * DOUT];   // iter-0 output [b][j][h]
__device__ float g_pred[BB * NOUT * DIN];     // pred [b][j][d]
__device__ float g_phi1[BB * NI * NOUT];      // phi iter-1 [b][i][j]
__device__ float g_phiT[NOUT * NI * BB];      // phi transposed [j][i][b]

__device__ __forceinline__ float2 ffma2(const float2 a, const float2 b, const float2 c) {
    float2 d;
    asm("fma.rn.f32x2 %0, %1, %2, %3;"
        : "=l"(*reinterpret_cast<unsigned long long*>(&d))
        : "l"(*reinterpret_cast<const unsigned long long*>(&a)),
          "l"(*reinterpret_cast<const unsigned long long*>(&b)),
          "l"(*reinterpret_cast<const unsigned long long*>(&c)));
    return d;
}
__device__ __forceinline__ float2 fdup(float v) { return make_float2(v, v); }

// ---------------- K1: f_a = sigmoid(x . W_A + b_A) -> g_faT[i][b] ---------
__global__ __launch_bounds__(256) void k_fa(const float* __restrict__ x,
                                            const float* __restrict__ WA,
                                            const float* __restrict__ bA) {
    const int row = blockIdx.x * 8 + (threadIdx.x >> 5);   // b*NI + i
    const int lane = threadIdx.x & 31;
    const float4* xr = reinterpret_cast<const float4*>(x) + (size_t)row * (DIN / 4);
    const float4* w4 = reinterpret_cast<const float4*>(WA);
    float s = 0.f;
#pragma unroll
    for (int q = 0; q < 8; q++) {
        float4 xv = xr[lane + q * 32], wv = w4[lane + q * 32];
        s += xv.x * wv.x + xv.y * wv.y + xv.z * wv.z + xv.w * wv.w;
    }
#pragma unroll
    for (int o = 16; o; o >>= 1) s += __shfl_xor_sync(0xffffffffu, s, o);
    if (lane == 0) {
        const int b = row >> 10, i = row & (NI - 1);
        float tot = s + bA[0];
        g_faT[i * BB + b] = 1.f / (1.f + __expf(-tot));
    }
}

// ---------------- K2: phi0 transposed [j][i][b] ---------------------------
__global__ __launch_bounds__(256) void k_phi0(const float* __restrict__ bu,
                                              const float* __restrict__ bn) {
    const int p = blockIdx.x * 256 + threadIdx.x;   // (j,i)
    const int j = p >> 10, i = p & (NI - 1);
    const float cu = bu[i * NOUT + j] * (1.0f / 64.0f) - bn[i * NOUT + j] * (63.0f / 64.0f);
    const float4* fa = reinterpret_cast<const float4*>(&g_faT[i * BB]);
    float4* dst = reinterpret_cast<float4*>(&g_phiT[((size_t)j * NI + i) * BB]);
#pragma unroll
    for (int q = 0; q < 8; q++) {
        float4 v = fa[q];
        dst[q] = make_float4(v.x * cu, v.y * cu, v.z * cu, v.w * cu);
    }
}

// ---------------- K3: out[b,j,h] = sum_i phiT[j,i,b]*Wm[i,j,h] ------------
// Block (hb 0..7, j 0..63), 128 thr. Tile 32b x 128h, KT=16. Micro 4b x 8h.
// m0=(lane&7)*4 (4 b), n0=(w*4+(lane>>3))*8 (8 h). All LDS conflict-free.
template <int MODE>
__global__ __launch_bounds__(128) void k_mem(const float* __restrict__ Wm,
                                             float* __restrict__ outp) {
    const int j = blockIdx.y, hb = blockIdx.x;
    __shared__ float As[2][KT][BB];      // 4KB
    __shared__ float Bs[2][KT][128];     // 16KB
    const int tid = threadIdx.x, lane = tid & 31, w = tid >> 5;
    const int m0 = (lane & 7) * 4;
    const int n0 = (w * 4 + (lane >> 3)) * 8;
    const int fbr = tid >> 3, fbc = tid & 7;        // B: row, col4 base (q*8)
    const int far_ = tid >> 3, fac = (tid & 7) * 4; // A: row, 4 b's
    const float* WmB = Wm + (size_t)j * DOUT + (size_t)hb * 128;
    const float* Ab = g_phiT + (size_t)j * (NI * BB);

    float2 acc[4][4];
#pragma unroll
    for (int a = 0; a < 4; a++)
#pragma unroll
        for (int h = 0; h < 4; h++) acc[a][h] = make_float2(0.f, 0.f);

    float4 bR[4]; float4 aR;
#pragma unroll
    for (int q = 0; q < 4; q++)
        bR[q] = *reinterpret_cast<const float4*>(WmB + (size_t)fbr * (NOUT * DOUT) + (size_t)(fbc + q * 8) * 4);
    aR = *reinterpret_cast<const float4*>(Ab + (size_t)far_ * BB + fac);
#pragma unroll
    for (int q = 0; q < 4; q++)
        *reinterpret_cast<float4*>(&Bs[0][fbr][(fbc + q * 8) * 4]) = bR[q];
    *reinterpret_cast<float4*>(&As[0][far_][fac]) = aR;
    __syncthreads();

    const int NT = NI / KT;  // 64
    for (int t = 0; t < NT; t++) {
        const int cur = t & 1;
        const bool more = (t + 1 < NT);
        if (more) {
            const int i0 = (t + 1) * KT;
#pragma unroll
            for (int q = 0; q < 4; q++)
                bR[q] = *reinterpret_cast<const float4*>(WmB + (size_t)(i0 + fbr) * (NOUT * DOUT) + (size_t)(fbc + q * 8) * 4);
            aR = *reinterpret_cast<const float4*>(Ab + (size_t)(i0 + far_) * BB + fac);
        }
#pragma unroll
        for (int k = 0; k < KT; k++) {
            float4 av = *reinterpret_cast<const float4*>(&As[cur][k][m0]);
            float4 b0 = *reinterpret_cast<const float4*>(&Bs[cur][k][n0]);
            float4 b1 = *reinterpret_cast<const float4*>(&Bs[cur][k][n0 + 4]);
            float2 bp[4] = {make_float2(b0.x, b0.y), make_float2(b0.z, b0.w),
                            make_float2(b1.x, b1.y), make_float2(b1.z, b1.w)};
            float2 ad[4] = {fdup(av.x), fdup(av.y), fdup(av.z), fdup(av.w)};
#pragma unroll
            for (int a = 0; a < 4; a++)
#pragma unroll
                for (int h = 0; h < 4; h++) acc[a][h] = ffma2(ad[a], bp[h], acc[a][h]);
        }
        if (more) {
            const int nxt = 1 - cur;
#pragma unroll
            for (int q = 0; q < 4; q++)
                *reinterpret_cast<float4*>(&Bs[nxt][fbr][(fbc + q * 8) * 4]) = bR[q];
            *reinterpret_cast<float4*>(&As[nxt][far_][fac]) = aR;
        }
        __syncthreads();
    }
    float* dst = (MODE == 0) ? g_xout0 : outp;
#pragma unroll
    for (int a = 0; a < 4; a++) {
        const int b = m0 + a;
        float* o = dst + ((size_t)(b * NOUT + j)) * DOUT + hb * 128 + n0;
        *reinterpret_cast<float4*>(o) =
            make_float4(acc[a][0].x, acc[a][0].y, acc[a][1].x, acc[a][1].y);
        *reinterpret_cast<float4*>(o + 4) =
            make_float4(acc[a][2].x, acc[a][2].y, acc[a][3].x, acc[a][3].y);
    }
}

// ---------------- K4: pred = xout0 @ WG + bG  (2048x1024x1024) ------------
// Block (nb 0..7, mb 0..15), 256 thr. Tile 128m x 128n, KT=16. Micro 8m x 8n.
// m rows: {ma..ma+3, ma+32..ma+35}; pairs along m (natural); b dup via MOV.
__global__ __launch_bounds__(256) void k_pred(const float* __restrict__ WG,
                                              const float* __restrict__ bG) {
    const int nb = blockIdx.x, mb = blockIdx.y;
    const int mBase = mb * 128, nBase = nb * 128;
    __shared__ float As[2][KT][128];   // 16KB  [k][m]
    __shared__ float Bs[2][KT][128];   // 16KB  [k][n]
    const int tid = threadIdx.x, lane = tid & 31, w = tid >> 5;
    const int ma = (w >> 2) * 64 + (lane & 7) * 4;       // conflict-free 16B stride
    const int n0 = (w & 3) * 32 + (lane >> 3) * 8;
    const int fam = tid & 127, fak = (tid >> 7) * 8;     // A: row m, 8 k's
    const int fbr = tid >> 4, fbn = tid & 15;            // B: row k, col4 base

    float2 acc[4][8];
#pragma unroll
    for (int p = 0; p < 4; p++)
#pragma unroll
        for (int n = 0; n < 8; n++) acc[p][n] = make_float2(0.f, 0.f);

    float4 aR[2], bR[2];
#pragma unroll
    for (int q = 0; q < 2; q++)
        aR[q] = *reinterpret_cast<const float4*>(g_xout0 + (size_t)(mBase + fam) * DOUT + fak + q * 4);
#pragma unroll
    for (int q = 0; q < 2; q++)
        bR[q] = *reinterpret_cast<const float4*>(WG + (size_t)fbr * DIN + nBase + (fbn + q * 16) * 4);
#pragma unroll
    for (int q = 0; q < 2; q++) {
        As[0][fak + q * 4 + 0][fam] = (&aR[q].x)[0];
        As[0][fak + q * 4 + 1][fam] = (&aR[q].x)[1];
        As[0][fak + q * 4 + 2][fam] = (&aR[q].x)[2];
        As[0][fak + q * 4 + 3][fam] = (&aR[q].x)[3];
    }
#pragma unroll
    for (int q = 0; q < 2; q++)
        *reinterpret_cast<float4*>(&Bs[0][fbr][(fbn + q * 16) * 4]) = bR[q];
    __syncthreads();

    const int NT = DOUT / KT;
    for (int t = 0; t < NT; t++) {
        const int cur = t & 1;
        const bool more = (t + 1 < NT);
        if (more) {
            const int h0 = (t + 1) * KT;
#pragma unroll
            for (int q = 0; q < 2; q++)
                aR[q] = *reinterpret_cast<const float4*>(g_xout0 + (size_t)(mBase + fam) * DOUT + h0 + fak + q * 4);
#pragma unroll
            for (int q = 0; q < 2; q++)
                bR[q] = *reinterpret_cast<const float4*>(WG + (size_t)(h0 + fbr) * DIN + nBase + (fbn + q * 16) * 4);
        }
#pragma unroll
        for (int k = 0; k < KT; k++) {
            float4 a0 = *reinterpret_cast<const float4*>(&As[cur][k][ma]);
            float4 a1 = *reinterpret_cast<const float4*>(&As[cur][k][ma + 32]);
            float4 b0 = *reinterpret_cast<const float4*>(&Bs[cur][k][n0]);
            float4 b1 = *reinterpret_cast<const float4*>(&Bs[cur][k][n0 + 4]);
            float2 ap[4] = {make_float2(a0.x, a0.y), make_float2(a0.z, a0.w),
                            make_float2(a1.x, a1.y), make_float2(a1.z, a1.w)};
            float2 bd[8] = {fdup(b0.x), fdup(b0.y), fdup(b0.z), fdup(b0.w),
                            fdup(b1.x), fdup(b1.y), fdup(b1.z), fdup(b1.w)};
#pragma unroll
            for (int p = 0; p < 4; p++)
#pragma unroll
                for (int n = 0; n < 8; n++) acc[p][n] = ffma2(ap[p], bd[n], acc[p][n]);
        }
        if (more) {
            const int nxt = 1 - cur;
#pragma unroll
            for (int q = 0; q < 2; q++) {
                As[nxt][fak + q * 4 + 0][fam] = (&aR[q].x)[0];
                As[nxt][fak + q * 4 + 1][fam] = (&aR[q].x)[1];
                As[nxt][fak + q * 4 + 2][fam] = (&aR[q].x)[2];
                As[nxt][fak + q * 4 + 3][fam] = (&aR[q].x)[3];
            }
#pragma unroll
            for (int q = 0; q < 2; q++)
                *reinterpret_cast<float4*>(&Bs[nxt][fbr][(fbn + q * 16) * 4]) = bR[q];
        }
        __syncthreads();
    }
    const float4 bg0 = *reinterpret_cast<const float4*>(bG + nBase + n0);
    const float4 bg1 = *reinterpret_cast<const float4*>(bG + nBase + n0 + 4);
#pragma unroll
    for (int p = 0; p < 4; p++) {
        const int r0 = mBase + ma + (p & 1) * 2 + (p >> 1) * 32;
        float* o = g_pred + (size_t)r0 * DIN + nBase + n0;
        *reinterpret_cast<float4*>(o) =
            make_float4(acc[p][0].x + bg0.x, acc[p][1].x + bg0.y,
                        acc[p][2].x + bg0.z, acc[p][3].x + bg0.w);
        *reinterpret_cast<float4*>(o + 4) =
            make_float4(acc[p][4].x + bg1.x, acc[p][5].x + bg1.y,
                        acc[p][6].x + bg1.z, acc[p][7].x + bg1.w);
        float* o1 = o + DIN;
        *reinterpret_cast<float4*>(o1) =
            make_float4(acc[p][0].y + bg0.x, acc[p][1].y + bg0.y,
                        acc[p][2].y + bg0.z, acc[p][3].y + bg0.w);
        *reinterpret_cast<float4*>(o1 + 4) =
            make_float4(acc[p][4].y + bg1.x, acc[p][5].y + bg1.y,
                        acc[p][6].y + bg1.z, acc[p][7].y + bg1.w);
    }
}

// ---------------- K5: S=(x.pred^T)*scale -> softmax -> phi1[b][i][j] ------
// Block (it 0..7, b 0..31), 256 thr. Tile 128i x 64j, KT=16. Micro 8i x 4j.
// m0 = w*16 + (lane>>4)*8 (8 i, pairs along i); j0 = (lane&15)*4 (dup via MOV).
__global__ __launch_bounds__(256) void k_sim(const float* __restrict__ x,
                                             const float* __restrict__ bu,
                                             const float* __restrict__ bn) {
    const int i0 = blockIdx.x * 128;
    const int b = blockIdx.y;
    __shared__ float As[2][KT][128];   // 16KB [k][i]
    __shared__ float Bs[2][KT][NOUT];  //  8KB [k][j]
    const int tid = threadIdx.x, lane = tid & 31, w = tid >> 5;
    const int m0 = w * 16 + (lane >> 4) * 8;
    const int j0 = (lane & 15) * 4;
    const int fai = tid & 127, fak = (tid >> 7) * 8;
    const int fbj = tid & 63, fbk = (tid >> 6) * 4;

    const float* Arow = x + ((size_t)b * NI + i0 + fai) * DIN;
    const float* Brow = g_pred + ((size_t)b * NOUT + fbj) * DIN;

    float2 acc[4][4];  // [ipair][j]
#pragma unroll
    for (int p = 0; p < 4; p++)
#pragma unroll
        for (int n = 0; n < 4; n++) acc[p][n] = make_float2(0.f, 0.f);

    float4 aR[2]; float4 bR;
#pragma unroll
    for (int q = 0; q < 2; q++)
        aR[q] = *reinterpret_cast<const float4*>(Arow + fak + q * 4);
    bR = *reinterpret_cast<const float4*>(Brow + fbk);
#pragma unroll
    for (int q = 0; q < 2; q++) {
        As[0][fak + q * 4 + 0][fai] = (&aR[q].x)[0];
        As[0][fak + q * 4 + 1][fai] = (&aR[q].x)[1];
        As[0][fak + q * 4 + 2][fai] = (&aR[q].x)[2];
        As[0][fak + q * 4 + 3][fai] = (&aR[q].x)[3];
    }
    Bs[0][fbk + 0][fbj] = bR.x;
    Bs[0][fbk + 1][fbj] = bR.y;
    Bs[0][fbk + 2][fbj] = bR.z;
    Bs[0][fbk + 3][fbj] = bR.w;
    __syncthreads();

    const int NT = DIN / KT;
    for (int t = 0; t < NT; t++) {
        const int cur = t & 1;
        const bool more = (t + 1 < NT);
        if (more) {
            const int d0 = (t + 1) * KT;
#pragma unroll
            for (int q = 0; q < 2; q++)
                aR[q] = *reinterpret_cast<const float4*>(Arow + d0 + fak + q * 4);
            bR = *reinterpret_cast<const float4*>(Brow + d0 + fbk);
        }
#pragma unroll
        for (int k = 0; k < KT; k++) {
            float4 a0 = *reinterpret_cast<const float4*>(&As[cur][k][m0]);
            float4 a1 = *reinterpret_cast<const float4*>(&As[cur][k][m0 + 4]);
            float4 bv = *reinterpret_cast<const float4*>(&Bs[cur][k][j0]);
            float2 ap[4] = {make_float2(a0.x, a0.y), make_float2(a0.z, a0.w),
                            make_float2(a1.x, a1.y), make_float2(a1.z, a1.w)};
            float2 bd[4] = {fdup(bv.x), fdup(bv.y), fdup(bv.z), fdup(bv.w)};
#pragma unroll
            for (int p = 0; p < 4; p++)
#pragma unroll
                for (int n = 0; n < 4; n++) acc[p][n] = ffma2(ap[p], bd[n], acc[p][n]);
        }
        if (more) {
            const int nxt = 1 - cur;
#pragma unroll
            for (int q = 0; q < 2; q++) {
                As[nxt][fak + q * 4 + 0][fai] = (&aR[q].x)[0];
                As[nxt][fak + q * 4 + 1][fai] = (&aR[q].x)[1];
                As[nxt][fak + q * 4 + 2][fai] = (&aR[q].x)[2];
                As[nxt][fak + q * 4 + 3][fai] = (&aR[q].x)[3];
            }
            Bs[nxt][fbk + 0][fbj] = bR.x;
            Bs[nxt][fbk + 1][fbj] = bR.y;
            Bs[nxt][fbk + 2][fbj] = bR.z;
            Bs[nxt][fbk + 3][fbj] = bR.w;
        }
        __syncthreads();
    }

    // softmax over 64 j: each row owned by 16 lanes (same lane>>4), 4 j each
    const float scale = 0.03125f;  // 1024^-0.5
#pragma unroll
    for (int p = 0; p < 4; p++) {
#pragma unroll
        for (int half = 0; half < 2; half++) {
            const int r = i0 + m0 + 2 * p + half;
            float v[4];
#pragma unroll
            for (int n = 0; n < 4; n++)
                v[n] = (half ? acc[p][n].y : acc[p][n].x) * scale;
            float mx = fmaxf(fmaxf(v[0], v[1]), fmaxf(v[2], v[3]));
            mx = fmaxf(mx, __shfl_xor_sync(0xffffffffu, mx, 1));
            mx = fmaxf(mx, __shfl_xor_sync(0xffffffffu, mx, 2));
            mx = fmaxf(mx, __shfl_xor_sync(0xffffffffu, mx, 4));
            mx = fmaxf(mx, __shfl_xor_sync(0xffffffffu, mx, 8));
            float e[4], s = 0.f;
#pragma unroll
            for (int n = 0; n < 4; n++) { e[n] = __expf(v[n] - mx); s += e[n]; }
            s += __shfl_xor_sync(0xffffffffu, s, 1);
            s += __shfl_xor_sync(0xffffffffu, s, 2);
            s += __shfl_xor_sync(0xffffffffu, s, 4);
            s += __shfl_xor_sync(0xffffffffu, s, 8);
            const float inv = 1.f / s;
            const float fa = g_faT[r * BB + b];
            const float4 bu4 = *reinterpret_cast<const float4*>(bu + (size_t)r * NOUT + j0);
            const float4 bn4 = *reinterpret_cast<const float4*>(bn + (size_t)r * NOUT + j0);
            float* o = g_phi1 + ((size_t)b * NI + r) * NOUT + j0;
            *reinterpret_cast<float4*>(o) = make_float4(
                fa * ((bu4.x + bn4.x) * e[0] * inv - bn4.x),
                fa * ((bu4.y + bn4.y) * e[1] * inv - bn4.y),
                fa * ((bu4.z + bn4.z) * e[2] * inv - bn4.z),
                fa * ((bu4.w + bn4.w) * e[3] * inv - bn4.w));
        }
    }
}

// ---------------- K6: transpose phi1 [b][i][j] -> phiT [j][i][b] ----------
__global__ __launch_bounds__(256) void k_tr() {
    const int i = blockIdx.x;
    __shared__ float t[32][65];
    const int tid = threadIdx.x;
#pragma unroll
    for (int q = 0; q < 8; q++) {
        int idx = tid + q * 256;
        int bb = idx >> 6, j = idx & 63;
        t[bb][j] = g_phi1[((size_t)bb * NI + i) * NOUT + j];
    }
    __syncthreads();
#pragma unroll
    for (int q = 0; q < 8; q++) {
        int idx = tid + q * 256;
        int j = idx >> 5, bb = idx & 31;
        g_phiT[((size_t)j * NI + i) * BB + bb] = t[bb][j];
    }
}

// ---------------- launch ---------------------------------------------------
extern "C" void kernel_launch(void* const* d_in, const int* in_sizes, int n_in,
                              void* d_out, int out_size) {
    const float* x  = (const float*)d_in[0];
    const float* WA = (const float*)d_in[1];
    const float* bA = (const float*)d_in[2];
    const float* Wm = (const float*)d_in[3];
    const float* WG = (const float*)d_in[4];
    const float* bG = (const float*)d_in[5];
    const float* bu = (const float*)d_in[6];
    const float* bn = (const float*)d_in[7];
    float* out = (float*)d_out;

    k_fa<<<4096, 256>>>(x, WA, bA);
    k_phi0<<<256, 256>>>(bu, bn);
    k_mem<0><<<dim3(8, 64), 128>>>(Wm, nullptr);
    k_pred<<<dim3(8, 16), 256>>>(WG, bG);
    k_sim<<<dim3(8, 32), 256>>>(x, bu, bn);
    k_tr<<<NI, 256>>>();
    k_mem<1><<<dim3(8, 64), 128>>>(Wm, out);
}